// round 3
// baseline (speedup 1.0000x reference)
#include <cuda_runtime.h>
#include <cuda_bf16.h>

#define BB 32
#define CC 64
#define TT 2048
#define KK 16
#define NST 6

#define TILE 128
#define HALO_L 15                 // causal window reach (K-1)
#define HALO_R 3                  // pooling reach (+1 for rolling-sum lookahead)
#define ROW_FILL (TILE + HALO_L + HALO_R)   // 146 entries filled
#define PITCH 147                 // odd pitch -> conflict-free across c
#define WPAD 97                   // 96 W entries padded to odd pitch
#define NTHREADS 256
#define ITEMS 32                  // contiguous t's per thread

__device__ float g_means[BB * CC];

// ---------------------------------------------------------------------------
// Kernel 1: per-(b,c) mean over T
// ---------------------------------------------------------------------------
__global__ void mean_kernel(const float* __restrict__ x) {
    int row = blockIdx.x;                 // b*C + c
    const float* xr = x + (size_t)row * TT;
    float s = 0.f;
    for (int t = threadIdx.x; t < TT; t += blockDim.x) s += xr[t];
    __shared__ float red[8];
    #pragma unroll
    for (int o = 16; o > 0; o >>= 1) s += __shfl_down_sync(0xffffffffu, s, o);
    if ((threadIdx.x & 31) == 0) red[threadIdx.x >> 5] = s;
    __syncthreads();
    if (threadIdx.x < 8) {
        s = red[threadIdx.x];
        #pragma unroll
        for (int o = 4; o > 0; o >>= 1) s += __shfl_down_sync(0xffu, s, o);
        if (threadIdx.x == 0) g_means[row] = s * (1.0f / TT);
    }
}

// ---------------------------------------------------------------------------
// Hot loop, templated on EDGE (boundary tiles need max/min validity checks).
// Thread owns channel c and ITEMS contiguous t's; x window lives in registers.
// ---------------------------------------------------------------------------
template <bool EDGE>
__device__ __forceinline__ void process_items(
    const float* __restrict__ xc,   // xc[tl] == x[b,c,t0+tl]
    const float* __restrict__ w,    // 96 per-channel weights (registers)
    const float* __restrict__ bs2,  // bias + w[k][1]*g_mean (registers)
    float* __restrict__ out, int b, int t0, int tl0, int c)
{
    // Rolling window: xw[i] = x[t - 15 + i], t = t0 + tl
    float xw[18];
    #pragma unroll
    for (int i = 0; i < 18; i++) xw[i] = xc[tl0 - 15 + i];

    float s  = xw[13] + xw[14] + xw[15] + xw[16] + xw[17];
    float s2 = xw[13]*xw[13] + xw[14]*xw[14] + xw[15]*xw[15]
             + xw[16]*xw[16] + xw[17]*xw[17];

    #pragma unroll 4
    for (int it = 0; it < ITEMS; it++) {
        const int tl = tl0 + it;
        const int tg = t0 + tl;

        const float xv   = xw[15];
        const float avg  = s  * 0.2f;
        const float avg2 = s2 * 0.2f;
        const float sd   = sqrtf(fmaxf(avg2 - avg * avg, 1e-6f));
        const float d    = xv - avg;
        const float tm   = d * d * d;

        float mx, mn;
        if (EDGE) {
            mx = -3.402823466e38f; mn = 3.402823466e38f;
            #pragma unroll
            for (int j = -2; j <= 2; j++) {
                int g = tg + j;
                if (g >= 0 && g < TT) {
                    float v = xw[15 + j];
                    mx = fmaxf(mx, v); mn = fminf(mn, v);
                }
            }
        } else {
            mx = fmaxf(fmaxf(fmaxf(xw[13], xw[14]), fmaxf(xw[15], xw[16])), xw[17]);
            mn = fminf(fminf(fminf(xw[13], xw[14]), fminf(xw[15], xw[16])), xw[17]);
        }

        // grouped 1x1 conv (g_mean term pre-folded into bs2)
        float kern[KK];
        #pragma unroll
        for (int k = 0; k < KK; k++) {
            float a = bs2[k];
            a = fmaf(w[k * NST + 0], xv, a);
            a = fmaf(w[k * NST + 2], sd, a);
            a = fmaf(w[k * NST + 3], tm, a);
            a = fmaf(w[k * NST + 4], mx, a);
            a = fmaf(w[k * NST + 5], mn, a);
            kern[k] = a;
        }

        // softmax over |kern| (args ~0.2, no max-sub needed; clamp for safety),
        // sign folded into exp values, gather taps are exactly xw[0..15]
        float sum = 0.f;
        float acc = 0.f;
        #pragma unroll
        for (int k = 0; k < KK; k++) {
            float a  = fminf(fabsf(kern[k]), 80.f);
            float ev = __expf(a);
            sum += ev;
            float sv = (kern[k] > 0.f) ? ev : (kern[k] < 0.f ? -ev : 0.f);
            acc = fmaf(xw[k], sv, acc);
        }

        out[((size_t)b * TT + tg) * CC + c] = acc * (1.0f / sum);

        // roll window + incremental pooling sums
        float xnew = xc[tl + 3];
        s  += xnew - xw[13];
        s2 = fmaf(xnew, xnew, s2 - xw[13] * xw[13]);
        #pragma unroll
        for (int i = 0; i < 17; i++) xw[i] = xw[i + 1];
        xw[17] = xnew;
    }
}

// ---------------------------------------------------------------------------
// Kernel 2: fused stats -> conv -> softmax-attn -> causal gather
// ---------------------------------------------------------------------------
extern __shared__ float smem[];

__global__ __launch_bounds__(NTHREADS, 1)
void ddst_main_kernel(const float* __restrict__ x,
                      const float* __restrict__ W,
                      const float* __restrict__ bias,
                      float* __restrict__ out) {
    float* xs = smem;                   // [C][PITCH]
    float* ws = smem + CC * PITCH;      // [C][WPAD]

    const int ntiles = TT / TILE;
    const int b    = blockIdx.x / ntiles;
    const int tile = blockIdx.x % ntiles;
    const int t0   = tile * TILE;
    const int tid  = threadIdx.x;
    const int warp = tid >> 5;
    const int lane = tid & 31;

    const float* xb = x + (size_t)b * CC * TT;

    // x tile + halo: one warp per channel row, no div/mod
    for (int cr = warp; cr < CC; cr += NTHREADS / 32) {
        const float* src = xb + (size_t)cr * TT;
        float* dst = xs + cr * PITCH;
        for (int j = lane; j < ROW_FILL; j += 32) {
            int gt = t0 - HALO_L + j;
            dst[j] = (gt >= 0 && gt < TT) ? src[gt] : 0.f;
        }
    }
    // W staging: coalesced global read, odd-pitch shared
    for (int cr = warp; cr < CC; cr += NTHREADS / 32) {
        const float* src = W + cr * (KK * NST);
        float* dst = ws + cr * WPAD;
        for (int j = lane; j < KK * NST; j += 32) dst[j] = src[j];
    }
    __syncthreads();

    const int c   = tid & (CC - 1);
    const int tl0 = (tid >> 6) * ITEMS;    // 0, 32, 64, 96

    float w[KK * NST];
    #pragma unroll
    for (int j = 0; j < KK * NST; j++) w[j] = ws[c * WPAD + j];

    const float gm = g_means[b * CC + c];
    float bs2[KK];
    #pragma unroll
    for (int k = 0; k < KK; k++)
        bs2[k] = fmaf(w[k * NST + 1], gm, __ldg(&bias[c * KK + k]));

    const float* xc = xs + c * PITCH + HALO_L;

    if (tile == 0 || tile == ntiles - 1)
        process_items<true>(xc, w, bs2, out, b, t0, tl0, c);
    else
        process_items<false>(xc, w, bs2, out, b, t0, tl0, c);
}

// ---------------------------------------------------------------------------
extern "C" void kernel_launch(void* const* d_in, const int* in_sizes, int n_in,
                              void* d_out, int out_size) {
    const float* x    = (const float*)d_in[0];   // [B, C, T]
    const float* W    = (const float*)d_in[1];   // [C, K, 6]
    const float* bias = (const float*)d_in[2];   // [C, K]
    float* out = (float*)d_out;                  // [B, T, C]

    (void)in_sizes; (void)n_in; (void)out_size;

    mean_kernel<<<BB * CC, 256>>>(x);

    const int smem_bytes = (CC * PITCH + CC * WPAD) * (int)sizeof(float);
    cudaFuncSetAttribute(ddst_main_kernel,
                         cudaFuncAttributeMaxDynamicSharedMemorySize, smem_bytes);
    ddst_main_kernel<<<BB * (TT / TILE), NTHREADS, smem_bytes>>>(x, W, bias, out);
}

// round 4
// speedup vs baseline: 1.1062x; 1.1062x over previous
#include <cuda_runtime.h>
#include <cuda_bf16.h>

#define BB 32
#define CC 64
#define TT 2048
#define KK 16
#define NST 6

#define TILE 64
#define HALO_L 15                    // causal window reach (K-1)
#define HALO_R 5                     // pooling reach for last strip item (+3+2)
#define ROWF (TILE + HALO_L + HALO_R)   // 84 filled
#define PITCH 85                     // odd -> conflict-free across c
#define WPAD 97                      // odd pitch for W staging
#define NTH 128
#define NTILES (TT / TILE)           // 32

__device__ float g_means[BB * CC];

__device__ __forceinline__ float sqrt_approx(float x) {
    float r; asm("sqrt.approx.f32 %0, %1;" : "=f"(r) : "f"(x)); return r;
}
__device__ __forceinline__ float rcp_approx(float x) {
    float r; asm("rcp.approx.f32 %0, %1;" : "=f"(r) : "f"(x)); return r;
}
__device__ __forceinline__ float apply_sign(float ev, float k) {
    // ev > 0; returns ev with k's sign bit (sign(k)*ev; k==0 prob ~0)
    return __uint_as_float(__float_as_uint(ev) | (__float_as_uint(k) & 0x80000000u));
}

// ---------------------------------------------------------------------------
// Kernel 1: per-(b,c) mean over T
// ---------------------------------------------------------------------------
__global__ void mean_kernel(const float* __restrict__ x) {
    int row = blockIdx.x;
    const float* xr = x + (size_t)row * TT;
    float s = 0.f;
    for (int t = threadIdx.x; t < TT; t += blockDim.x) s += xr[t];
    __shared__ float red[8];
    #pragma unroll
    for (int o = 16; o > 0; o >>= 1) s += __shfl_down_sync(0xffffffffu, s, o);
    if ((threadIdx.x & 31) == 0) red[threadIdx.x >> 5] = s;
    __syncthreads();
    if (threadIdx.x < 8) {
        s = red[threadIdx.x];
        #pragma unroll
        for (int o = 4; o > 0; o >>= 1) s += __shfl_down_sync(0xffu, s, o);
        if (threadIdx.x == 0) g_means[row] = s * (1.0f / TT);
    }
}

// ---------------------------------------------------------------------------
// Strip of 4 contiguous t's: taps v[0..20] = x[t0+tl-15 .. t0+tl+5].
// Item m (0..3): gather taps v[m..m+15], pool window v[13+m..17+m].
// ---------------------------------------------------------------------------
template <bool EDGE>
__device__ __forceinline__ void do_strip(
    const float* __restrict__ xw,   // xw[j-15] valid for j in [0,20]
    const float* __restrict__ w,    // 80 regs: per k {w0, w2, w3, w4, w5}
    const float* __restrict__ bs2,  // bias + w1*g_mean
    float* __restrict__ outp,       // &out[b, t0+tl, c]; stride CC per t
    int tg0)                        // global t of item 0
{
    float v[21];
    #pragma unroll
    for (int j = 0; j < 21; j++) v[j] = xw[j - 15];

    // incremental pooling sums across the 4 items (short, in-strip chain only)
    float s  = v[13] + v[14] + v[15] + v[16] + v[17];
    float s2 = fmaf(v[13], v[13], fmaf(v[14], v[14],
               fmaf(v[15], v[15], fmaf(v[16], v[16], v[17] * v[17]))));

    #pragma unroll
    for (int m = 0; m < 4; m++) {
        const float xv   = v[15 + m];
        const float avg  = s * 0.2f;
        const float avg2 = s2 * 0.2f;
        const float sd   = sqrt_approx(fmaxf(fmaf(-avg, avg, avg2), 1e-6f));
        const float d    = xv - avg;
        const float tm   = d * d * d;

        float mx, mn;
        if (EDGE) {
            mx = -3.402823466e38f; mn = 3.402823466e38f;
            #pragma unroll
            for (int j = -2; j <= 2; j++) {
                int g = tg0 + m + j;
                if (g >= 0 && g < TT) {
                    float t = v[15 + m + j];
                    mx = fmaxf(mx, t); mn = fminf(mn, t);
                }
            }
        } else {
            float a = fmaxf(v[13 + m], v[14 + m]);
            float b2 = fmaxf(v[15 + m], v[16 + m]);
            mx = fmaxf(fmaxf(a, b2), v[17 + m]);
            float c = fminf(v[13 + m], v[14 + m]);
            float e = fminf(v[15 + m], v[16 + m]);
            mn = fminf(fminf(c, e), v[17 + m]);
        }

        // grouped 1x1 conv (w[k][1]*g_mean folded into bs2)
        float kern[KK];
        #pragma unroll
        for (int k = 0; k < KK; k++) {
            const float* wk = w + k * 5;
            float a = bs2[k];
            a = fmaf(wk[0], xv, a);
            a = fmaf(wk[1], sd, a);
            a = fmaf(wk[2], tm, a);
            a = fmaf(wk[3], mx, a);
            a = fmaf(wk[4], mn, a);
            kern[k] = a;
        }

        // softmax over |kern| (no max-sub needed: shift-invariant, args ~O(1)),
        // sign folded via copysign, gather taps straight from v[]
        float sum = 0.f, acc = 0.f;
        #pragma unroll
        for (int k = 0; k < KK; k++) {
            float ev = __expf(fabsf(kern[k]));   // FMUL(|x|*log2e) + MUFU.EX2
            sum += ev;
            acc = fmaf(v[m + k], apply_sign(ev, kern[k]), acc);
        }
        outp[m * CC] = acc * rcp_approx(sum);

        // advance pooling sums
        if (m < 3) {
            float vo = v[13 + m], vn = v[18 + m];
            s  += vn - vo;
            s2  = fmaf(vn, vn, fmaf(-vo, vo, s2));
        }
    }
}

// ---------------------------------------------------------------------------
// Kernel 2: fused stats -> conv -> softmax-attn -> causal gather
// CTA: 128 threads (c = tid&63, g = tid>>6), tile of 64 t's, one b.
// 3 CTAs/SM -> 12 warps/SM.
// ---------------------------------------------------------------------------
extern __shared__ float smem[];

__global__ __launch_bounds__(NTH, 3)
void ddst_main_kernel(const float* __restrict__ x,
                      const float* __restrict__ W,
                      const float* __restrict__ bias,
                      float* __restrict__ out) {
    float* xs = smem;                   // [C][PITCH]
    float* ws = smem + CC * PITCH;      // [C][WPAD]

    const int b    = blockIdx.x / NTILES;
    const int tile = blockIdx.x % NTILES;
    const int t0   = tile * TILE;
    const int tid  = threadIdx.x;
    const int warp = tid >> 5;
    const int lane = tid & 31;

    const float* xb = x + (size_t)b * CC * TT;

    // x tile + halo: warp per channel row (stride 4), zero outside [0,T)
    for (int cr = warp; cr < CC; cr += NTH / 32) {
        const float* src = xb + (size_t)cr * TT;
        float* dst = xs + cr * PITCH;
        for (int j = lane; j < ROWF; j += 32) {
            int gt = t0 - HALO_L + j;
            dst[j] = (gt >= 0 && gt < TT) ? src[gt] : 0.f;
        }
    }
    for (int cr = warp; cr < CC; cr += NTH / 32) {
        const float* src = W + cr * (KK * NST);
        float* dst = ws + cr * WPAD;
        for (int j = lane; j < KK * NST; j += 32) dst[j] = src[j];
    }
    __syncthreads();

    const int c = tid & (CC - 1);
    const int g = tid >> 6;          // 0 or 1

    // per-channel weights -> 80 registers (skip w[k][1], folded into bias)
    float w[KK * 5];
    #pragma unroll
    for (int k = 0; k < KK; k++) {
        const float* sw = ws + c * WPAD + k * NST;
        w[k * 5 + 0] = sw[0];
        w[k * 5 + 1] = sw[2];
        w[k * 5 + 2] = sw[3];
        w[k * 5 + 3] = sw[4];
        w[k * 5 + 4] = sw[5];
    }
    const float gm = g_means[b * CC + c];
    float bs2[KK];
    #pragma unroll
    for (int k = 0; k < KK; k++)
        bs2[k] = fmaf(ws[c * WPAD + k * NST + 1], gm, __ldg(&bias[c * KK + k]));

    const float* xc = xs + c * PITCH + HALO_L;   // xc[tl] == x[b,c,t0+tl]
    float* outb = out + ((size_t)b * TT + t0) * CC + c;

    const bool edge = (tile == 0) || (tile == NTILES - 1);
    if (edge) {
        #pragma unroll 2
        for (int i = 0; i < 8; i++) {
            int tl = g * 4 + i * 8;
            do_strip<true>(xc + tl, w, bs2, outb + tl * CC, t0 + tl);
        }
    } else {
        #pragma unroll 2
        for (int i = 0; i < 8; i++) {
            int tl = g * 4 + i * 8;
            do_strip<false>(xc + tl, w, bs2, outb + tl * CC, t0 + tl);
        }
    }
}

// ---------------------------------------------------------------------------
extern "C" void kernel_launch(void* const* d_in, const int* in_sizes, int n_in,
                              void* d_out, int out_size) {
    const float* x    = (const float*)d_in[0];   // [B, C, T]
    const float* W    = (const float*)d_in[1];   // [C, K, 6]
    const float* bias = (const float*)d_in[2];   // [C, K]
    float* out = (float*)d_out;                  // [B, T, C]

    (void)in_sizes; (void)n_in; (void)out_size;

    mean_kernel<<<BB * CC, 256>>>(x);

    const int smem_bytes = (CC * PITCH + CC * WPAD) * (int)sizeof(float);
    cudaFuncSetAttribute(ddst_main_kernel,
                         cudaFuncAttributeMaxDynamicSharedMemorySize, smem_bytes);
    ddst_main_kernel<<<BB * NTILES, NTH, smem_bytes>>>(x, W, bias, out);
}